// round 1
// baseline (speedup 1.0000x reference)
#include <cuda_runtime.h>
#include <cuda_bf16.h>

// SSIM loss, fused single-pass tiled kernel.
// pred/target: (16,3,512,512) f32; window: (3,1,11,11) f32 (separable Gaussian).
// Output: scalar f32 = 1 - mean(ssim_map).

#define IMG_H 512
#define IMG_W 512
#define BATCH 16
#define CHANS 3
#define TILE 32
#define RAD 5
#define PADT (TILE + 2 * RAD)   // 42
#define SPITCH (PADT + 2)       // 44 (avoid bank conflicts on +k access)
#define SSIM_C1 1.0e-4f
#define SSIM_C2 9.0e-4f

__device__ double g_accum;

__global__ void zero_accum_kernel() { g_accum = 0.0; }

__global__ __launch_bounds__(256)
void ssim_tile_kernel(const float* __restrict__ pred,
                      const float* __restrict__ target,
                      const float* __restrict__ window)
{
    __shared__ float g1d[16];
    __shared__ float sp[PADT][SPITCH];
    __shared__ float st[PADT][SPITCH];
    __shared__ float hb[5][PADT][TILE];
    __shared__ float wsum[8];

    const int tid  = threadIdx.x;
    const int lane = tid & 31;
    const int wrp  = tid >> 5;

    // Recover normalized 1-D Gaussian from center row of the 2-D window:
    // w2d[5][j] = g[5]*g[j], sum_j w2d[5][j] = g[5]  =>  g[j] = w2d[5][j]/rowsum
    if (tid == 0) {
        const float* wrow = window + RAD * 11;  // channel 0, center row
        float tmp[11];
        float s = 0.f;
        #pragma unroll
        for (int i = 0; i < 11; i++) { tmp[i] = wrow[i]; s += tmp[i]; }
        float inv = 1.0f / s;
        #pragma unroll
        for (int i = 0; i < 11; i++) g1d[i] = tmp[i] * inv;
    }

    const int tiles_x = IMG_W / TILE;          // 16
    const int tile_x  = blockIdx.x % tiles_x;
    const int tile_y  = blockIdx.x / tiles_x;
    const int img     = blockIdx.y;            // b*C + c
    const float* pbase = pred   + (size_t)img * IMG_H * IMG_W;
    const float* tbase = target + (size_t)img * IMG_H * IMG_W;

    const int x0 = tile_x * TILE - RAD;
    const int y0 = tile_y * TILE - RAD;

    // ---- Phase 1: load 42x42 halo tiles (zero-padded) -------------------
    for (int r = wrp; r < PADT; r += 8) {
        const int gy = y0 + r;
        const bool rowok = (gy >= 0) && (gy < IMG_H);
        const int rowoff = gy * IMG_W;
        {
            const int gx = x0 + lane;
            const bool ok = rowok && gx >= 0 && gx < IMG_W;
            sp[r][lane] = ok ? pbase[rowoff + gx] : 0.f;
            st[r][lane] = ok ? tbase[rowoff + gx] : 0.f;
        }
        const int lane2 = lane + 32;
        if (lane2 < PADT) {
            const int gx = x0 + lane2;
            const bool ok = rowok && gx >= 0 && gx < IMG_W;
            sp[r][lane2] = ok ? pbase[rowoff + gx] : 0.f;
            st[r][lane2] = ok ? tbase[rowoff + gx] : 0.f;
        }
    }
    __syncthreads();

    // ---- Phase 2: horizontal blur of 5 fields (42 rows x 32 cols) -------
    for (int r = wrp; r < PADT; r += 8) {
        float s1 = 0.f, s2 = 0.f, s3 = 0.f, s4 = 0.f, s5 = 0.f;
        #pragma unroll
        for (int k = 0; k < 11; k++) {
            const float w = g1d[k];
            const float p = sp[r][lane + k];
            const float t = st[r][lane + k];
            const float wp = w * p;
            const float wt = w * t;
            s1 += wp;
            s2 += wt;
            s3 = fmaf(wp, p, s3);
            s4 = fmaf(wt, t, s4);
            s5 = fmaf(wp, t, s5);
        }
        hb[0][r][lane] = s1;
        hb[1][r][lane] = s2;
        hb[2][r][lane] = s3;
        hb[3][r][lane] = s4;
        hb[4][r][lane] = s5;
    }
    __syncthreads();

    // ---- Phase 3: vertical blur + SSIM, 4 consecutive rows per thread ---
    const int yb = wrp * 4;   // output rows yb..yb+3 at column `lane`
    float a1[14], a2[14], a3[14], a4[14], a5[14];
    #pragma unroll
    for (int k = 0; k < 14; k++) {
        a1[k] = hb[0][yb + k][lane];
        a2[k] = hb[1][yb + k][lane];
        a3[k] = hb[2][yb + k][lane];
        a4[k] = hb[3][yb + k][lane];
        a5[k] = hb[4][yb + k][lane];
    }

    float num[4], den[4];
    #pragma unroll
    for (int j = 0; j < 4; j++) {
        float m1 = 0.f, m2 = 0.f, m3 = 0.f, m4 = 0.f, m5 = 0.f;
        #pragma unroll
        for (int k = 0; k < 11; k++) {
            const float w = g1d[k];
            m1 = fmaf(w, a1[j + k], m1);
            m2 = fmaf(w, a2[j + k], m2);
            m3 = fmaf(w, a3[j + k], m3);
            m4 = fmaf(w, a4[j + k], m4);
            m5 = fmaf(w, a5[j + k], m5);
        }
        const float mu1sq = m1 * m1;
        const float mu2sq = m2 * m2;
        const float mu12  = m1 * m2;
        const float s1sq  = m3 - mu1sq;
        const float s2sq  = m4 - mu2sq;
        const float s12   = m5 - mu12;
        num[j] = (2.f * mu12 + SSIM_C1) * (2.f * s12 + SSIM_C2);
        den[j] = (mu1sq + mu2sq + SSIM_C1) * (s1sq + s2sq + SSIM_C2);
    }

    // Combine 4 quotients into one division (MUFU pressure /4):
    // a/b + c/d = (a*d + c*b) / (b*d); den in [9e-8, ~4] so products stay normal.
    const float n01 = fmaf(num[0], den[1], num[1] * den[0]);
    const float d01 = den[0] * den[1];
    const float n23 = fmaf(num[2], den[3], num[3] * den[2]);
    const float d23 = den[2] * den[3];
    const float nall = fmaf(n01, d23, n23 * d01);
    const float dall = d01 * d23;
    float ssim4 = __fdividef(nall, dall);

    // ---- Reduce: warp shfl -> smem -> one double atomic per block -------
    #pragma unroll
    for (int o = 16; o > 0; o >>= 1)
        ssim4 += __shfl_xor_sync(0xffffffffu, ssim4, o);
    if (lane == 0) wsum[wrp] = ssim4;
    __syncthreads();
    if (tid == 0) {
        float bs = 0.f;
        #pragma unroll
        for (int i = 0; i < 8; i++) bs += wsum[i];
        atomicAdd(&g_accum, (double)bs);
    }
}

__global__ void finalize_kernel(float* __restrict__ out)
{
    const double n = (double)BATCH * CHANS * IMG_H * IMG_W;
    out[0] = (float)(1.0 - g_accum / n);
}

extern "C" void kernel_launch(void* const* d_in, const int* in_sizes, int n_in,
                              void* d_out, int out_size)
{
    const float* pred   = (const float*)d_in[0];
    const float* target = (const float*)d_in[1];
    const float* window = (const float*)d_in[2];
    float* out = (float*)d_out;
    (void)in_sizes; (void)n_in; (void)out_size;

    zero_accum_kernel<<<1, 1>>>();
    dim3 grid((IMG_W / TILE) * (IMG_H / TILE), BATCH * CHANS);  // (256, 48)
    ssim_tile_kernel<<<grid, 256>>>(pred, target, window);
    finalize_kernel<<<1, 1>>>(out);
}